// round 15
// baseline (speedup 1.0000x reference)
#include <cuda_runtime.h>
#include <cuda_fp16.h>
#include <math.h>
#include <stdint.h>

// ---------------------------------------------------------------------------
// Problem dims
// ---------------------------------------------------------------------------
#define M_ROWS  8192      // 4 * 2048
#define N_ATOMS 16384
#define DM      1024
#define LOG2E   1.4426950408889634f
#define CANDF   0.99448f  // 2^-0.008 — candidate threshold factor on w
#define MAXCAND 16
#define NTILES  (N_ATOMS / 128)   // 128 n-tiles per row

// ---------------------------------------------------------------------------
// Scratch (__device__ globals; allocation APIs are forbidden)
// ---------------------------------------------------------------------------
__device__ __half   g_Xf[(size_t)M_ROWS * DM];             // x * log2e, fp16
__device__ __half   g_Df[(size_t)N_ATOMS * DM];            // dict fp16 K-major
__device__ __half   g_DTf[(size_t)DM * N_ATOMS];           // dict^T fp16
__device__ __half   g_Wf[(size_t)M_ROWS * N_ATOMS];        // 256 MB fp16 weights
__device__ float    g_sum[M_ROWS];
__device__ unsigned g_tmax[(size_t)M_ROWS * NTILES];       // per-tile max bits
__device__ float    g_inv[M_ROWS];

// ---------------------------------------------------------------------------
// Low-level helpers (sm_80+ baseline PTX only — NO tcgen05 on plain sm_103)
// ---------------------------------------------------------------------------
__device__ __forceinline__ uint32_t smem_to_u32(const void* p) {
    uint32_t a;
    asm("{ .reg .u64 t; cvta.to.shared.u64 t, %1; cvt.u32.u64 %0, t; }"
        : "=r"(a) : "l"(p));
    return a;
}

#define CP16(dst, src) \
    asm volatile("cp.async.cg.shared.global [%0], [%1], 16;" \
                 :: "r"(dst), "l"(src) : "memory")
#define CP_COMMIT() asm volatile("cp.async.commit_group;" ::: "memory")
#define CP_WAIT2()  asm volatile("cp.async.wait_group 2;"  ::: "memory")

#define LDSM4(r0, r1, r2, r3, addr) \
    asm volatile("ldmatrix.sync.aligned.m8n8.x4.shared.b16 {%0,%1,%2,%3}, [%4];" \
        : "=r"(r0), "=r"(r1), "=r"(r2), "=r"(r3) : "r"(addr))

__device__ __forceinline__ void mma16816_f16(float* c, const uint32_t* a,
                                             const uint32_t* b) {
    asm volatile(
        "mma.sync.aligned.m16n8k16.row.col.f32.f16.f16.f32 "
        "{%0,%1,%2,%3}, {%4,%5,%6,%7}, {%8,%9}, {%0,%1,%2,%3};"
        : "+f"(c[0]), "+f"(c[1]), "+f"(c[2]), "+f"(c[3])
        : "r"(a[0]), "r"(a[1]), "r"(a[2]), "r"(a[3]), "r"(b[0]), "r"(b[1]));
}

__device__ __forceinline__ float ex2f(float x) {
    float y;
    asm("ex2.approx.ftz.f32 %0, %1;" : "=f"(y) : "f"(x));
    return y;
}

// ---------------------------------------------------------------------------
// Init: zero per-row sums and per-tile maxima
// ---------------------------------------------------------------------------
__global__ __launch_bounds__(256) void init_kernel(
    float* __restrict__ sum, unsigned* __restrict__ tmax)
{
    int i = blockIdx.x * blockDim.x + threadIdx.x;
    if (i < M_ROWS) sum[i] = 0.0f;
    int total_tm = M_ROWS * NTILES;
    for (int j = i; j < total_tm; j += gridDim.x * blockDim.x)
        tmax[j] = 0u;
}

// ---------------------------------------------------------------------------
// Conversion kernels
// ---------------------------------------------------------------------------
__global__ __launch_bounds__(256) void to_f16_scaled_kernel(
    const float* __restrict__ src, __half* __restrict__ dst, float scale, int n4)
{
    int i = blockIdx.x * blockDim.x + threadIdx.x;
    if (i >= n4) return;
    float4 v = reinterpret_cast<const float4*>(src)[i];
    ushort4 hv;
    hv.x = __half_as_ushort(__float2half_rn(v.x * scale));
    hv.y = __half_as_ushort(__float2half_rn(v.y * scale));
    hv.z = __half_as_ushort(__float2half_rn(v.z * scale));
    hv.w = __half_as_ushort(__float2half_rn(v.w * scale));
    reinterpret_cast<ushort4*>(dst)[i] = hv;
}

// dict [N_ATOMS][DM] fp32 -> Df fp16 (same layout) + DTf fp16 (transposed).
__global__ __launch_bounds__(256) void convert_dict_kernel(
    const float* __restrict__ dict, __half* __restrict__ Df,
    __half* __restrict__ DTf)
{
    __shared__ float t[32][33];
    const int bx = blockIdx.x;   // DM tile
    const int by = blockIdx.y;   // atom tile
    const int tx = threadIdx.x;
    const int ty = threadIdx.y;
    #pragma unroll
    for (int k = 0; k < 32; k += 8) {
        float v = dict[(size_t)(by * 32 + ty + k) * DM + bx * 32 + tx];
        t[ty + k][tx] = v;
        Df[(size_t)(by * 32 + ty + k) * DM + bx * 32 + tx] = __float2half_rn(v);
    }
    __syncthreads();
    #pragma unroll
    for (int k = 0; k < 32; k += 8) {
        size_t o = (size_t)(bx * 32 + ty + k) * N_ATOMS + by * 32 + tx;
        DTf[o] = __float2half_rn(t[tx][ty + k]);
    }
}

// ---------------------------------------------------------------------------
// Unified 1-term fp16 GEMM via ldmatrix + mma.sync, BK=32, 4-stage cp.async.
// out tile 128x128 = A[M,K] · B[N,K]^T
// MASK=true : out is __half WEIGHT w = 2^s (A pre-scaled by log2e), masked->0;
//             epilogue accumulates per-row sum (atomicAdd) and PER-TILE max
//             (atomicMax on float bits) of the fp16-rounded weights.
// MASK=false: out is float, row scaled by invp[row] (plain stores).
// 128 threads = 4 warps (2x2) of 64x64.
// Inner loop software-pipelined: B frags first, A-frag LDSM interleaved with
// previous A-frag's MMAs.
// smem rows: 64B data + 16B pad (80B) — conflict-free LDSM phases.
// ---------------------------------------------------------------------------
#define ROWB     80
#define TILE_B   (128 * ROWB)          // 10240
#define STAGE    (2 * TILE_B)          // 20480
#define NSTAGES  4
#define SMEMG    (NSTAGES * STAGE)     // 81920

template <bool MASK>
__global__ __launch_bounds__(128, 2) void gemm_f16(
    const __half* __restrict__ A, const __half* __restrict__ B, int Kdim,
    const int* __restrict__ mask, const float* __restrict__ invp,
    float* __restrict__ rsum, unsigned* __restrict__ tmax,
    void* __restrict__ outp, int out_ld)
{
    extern __shared__ char smem[];
    const uint32_t sbase = smem_to_u32(smem);
    const int tid  = threadIdx.x;
    const int warp = tid >> 5;
    const int lane = tid & 31;
    const int bm = blockIdx.y * 128;
    const int bn = blockIdx.x * 128;
    const int wm = (warp & 1) * 64;
    const int wn = (warp >> 1) * 64;

    // ldmatrix per-thread address components
    const int a_row = wm + (lane & 15);
    const int a_kh  = (lane >> 4) * 16;
    const int b_row = wn + ((lane >> 4) << 3) + (lane & 7);
    const int b_kh  = ((lane >> 3) & 1) * 16;

    float acc[4][8][4];
    #pragma unroll
    for (int mt = 0; mt < 4; mt++)
        #pragma unroll
        for (int nt = 0; nt < 8; nt++)
            #pragma unroll
            for (int r = 0; r < 4; r++) acc[mt][nt][r] = 0.0f;

    #define ISSUEG(cc, buf) do { \
        const int k0_ = (cc) << 5; \
        _Pragma("unroll") \
        for (int p = 0; p < 4; p++) { \
            const int v_   = tid + p * 128; \
            const int row_ = v_ >> 2; \
            const int c16_ = v_ & 3; \
            const uint32_t dst_ = sbase + (buf) * STAGE \
                                + row_ * ROWB + c16_ * 16; \
            const size_t ga_ = (size_t)(bm + row_) * Kdim + k0_ + c16_ * 8; \
            const size_t gb_ = (size_t)(bn + row_) * Kdim + k0_ + c16_ * 8; \
            CP16(dst_ + 0 * TILE_B, A + ga_); \
            CP16(dst_ + 1 * TILE_B, B + gb_); \
        } \
        CP_COMMIT(); \
    } while (0)

    ISSUEG(0, 0);
    ISSUEG(1, 1);
    ISSUEG(2, 2);

    const int NC = Kdim >> 5;
    for (int c = 0; c < NC; c++) {
        CP_WAIT2();          // chunk c resident (<=2 younger groups pending)
        __syncthreads();     // all warps past compute of chunk c-1
        if (c + 3 < NC) ISSUEG(c + 3, (c + 3) & 3);

        const uint32_t sA = sbase + (c & 3) * STAGE;
        const uint32_t sB = sA + TILE_B;

        #pragma unroll
        for (int ks = 0; ks < 2; ks++) {
            const uint32_t kb0 = ks * 32;

            uint32_t a[4][4], b[8][2];
            // B fragments first (4 LDSM covering nt 0..7)
            #pragma unroll
            for (int p = 0; p < 4; p++) {
                const uint32_t bd = sB + (b_row + p * 16) * ROWB + b_kh + kb0;
                LDSM4(b[2 * p][0], b[2 * p][1], b[2 * p + 1][0], b[2 * p + 1][1], bd);
            }
            // A[0], then interleave A[mt+1] load with A[mt]'s MMAs
            {
                const uint32_t ad = sA + (a_row + 0) * ROWB + a_kh + kb0;
                LDSM4(a[0][0], a[0][1], a[0][2], a[0][3], ad);
            }
            #pragma unroll
            for (int mt = 0; mt < 4; mt++) {
                if (mt < 3) {
                    const uint32_t ad = sA + (a_row + (mt + 1) * 16) * ROWB
                                      + a_kh + kb0;
                    LDSM4(a[mt + 1][0], a[mt + 1][1], a[mt + 1][2], a[mt + 1][3], ad);
                }
                #pragma unroll
                for (int nt = 0; nt < 8; nt++)
                    mma16816_f16(acc[mt][nt], a[mt], b[nt]);
            }
        }
    }
    #undef ISSUEG

    // Epilogue
    const int lr = lane >> 2;
    #pragma unroll
    for (int mt = 0; mt < 4; mt++) {
        #pragma unroll
        for (int half = 0; half < 2; half++) {
            const int rloc = bm + wm + mt * 16 + lr + half * 8;
            float inv = 1.0f;
            if (!MASK) inv = invp[rloc];
            const size_t rg = (size_t)rloc;
            float rsum_l = 0.0f, rmax_l = 0.0f;
            #pragma unroll
            for (int nt = 0; nt < 8; nt++) {
                const size_t o = rg * (size_t)out_ld
                               + (bn + wn + nt * 8 + (lane & 3) * 2);
                if (MASK) {
                    // fused softmax numerator: w = 2^s (A pre-scaled), mask->0
                    int2 mv = *reinterpret_cast<const int2*>(mask + o);
                    float2 v;
                    v.x = mv.x ? ex2f(acc[mt][nt][half * 2 + 0]) : 0.0f;
                    v.y = mv.y ? ex2f(acc[mt][nt][half * 2 + 1]) : 0.0f;
                    __half2 h2 = __float22half2_rn(v);
                    *reinterpret_cast<__half2*>((__half*)outp + o) = h2;
                    // accumulate from the ROUNDED values (consistency)
                    float2 vr = __half22float2(h2);
                    rsum_l += vr.x + vr.y;
                    rmax_l = fmaxf(rmax_l, fmaxf(vr.x, vr.y));
                } else {
                    float2 v;
                    v.x = acc[mt][nt][half * 2 + 0] * inv;
                    v.y = acc[mt][nt][half * 2 + 1] * inv;
                    *reinterpret_cast<float2*>((float*)outp + o) = v;
                }
            }
            if (MASK) {
                // quad reduce (lanes with same lr hold same row)
                rsum_l += __shfl_xor_sync(0xffffffffu, rsum_l, 1);
                rsum_l += __shfl_xor_sync(0xffffffffu, rsum_l, 2);
                rmax_l = fmaxf(rmax_l, __shfl_xor_sync(0xffffffffu, rmax_l, 1));
                rmax_l = fmaxf(rmax_l, __shfl_xor_sync(0xffffffffu, rmax_l, 2));
                if ((lane & 3) == 0) {
                    atomicAdd(rsum + rloc, rsum_l);
                    atomicMax(tmax + (size_t)rloc * NTILES + blockIdx.x,
                              __float_as_uint(rmax_l));
                }
            }
        }
    }
}

// ---------------------------------------------------------------------------
// Exact argmax, one block (256 thr) per row, using per-tile maxima:
// 1) reduce 128 tile maxima -> global max, thresh = max*CANDF
// 2) scan ONLY tiles whose max >= thresh (usually 1-2) for candidates
// 3) exact fp32 dot per candidate (block-wide over DM), winner by
//    (value, then smaller index). Also publishes invp = 1/sum.
// ---------------------------------------------------------------------------
#define BETTER(v, i, V, I) ((v) > (V) || ((v) == (V) && (i) < (I)))

__global__ __launch_bounds__(256) void argmax_rescue_kernel(
    const __half* __restrict__ Wf, const float* __restrict__ X,
    const float* __restrict__ Dict, const float* __restrict__ rsum,
    const unsigned* __restrict__ tmax, float* __restrict__ invp,
    float* __restrict__ argmax_out)
{
    const int row = blockIdx.x;
    const __half* wf = Wf + (size_t)row * N_ATOMS;
    const int tid = threadIdx.x;

    __shared__ float sred[256];
    __shared__ int   stile[MAXCAND];
    __shared__ int   stcount;
    __shared__ int   scand[MAXCAND];
    __shared__ int   scount;
    __shared__ float sthresh;

    if (tid == 0) { stcount = 0; scount = 0; }

    // 1) global max over tile maxima
    float tm = (tid < NTILES)
        ? __uint_as_float(tmax[(size_t)row * NTILES + tid]) : 0.0f;
    sred[tid] = tm;
    __syncthreads();
    for (int off = 128; off > 0; off >>= 1) {
        if (tid < off) sred[tid] = fmaxf(sred[tid], sred[tid + off]);
        __syncthreads();
    }
    if (tid == 0) sthresh = sred[0] * CANDF;
    __syncthreads();
    const float thresh = sthresh;

    // 2) qualifying tiles
    if (tid < NTILES && tm >= thresh) {
        int slot = atomicAdd(&stcount, 1);
        if (slot < MAXCAND) stile[slot] = tid;
    }
    __syncthreads();
    int tcnt = stcount; if (tcnt > MAXCAND) tcnt = MAXCAND;

    // scan qualifying tiles for candidates (128 weights per tile)
    for (int j = 0; j < tcnt; j++) {
        const int base = stile[j] * 128;
        if (tid < 128) {
            float w = __half2float(wf[base + tid]);
            if (w >= thresh) {
                int slot = atomicAdd(&scount, 1);
                if (slot < MAXCAND) scand[slot] = base + tid;
            }
        }
    }
    __syncthreads();
    int cnt = scount; if (cnt > MAXCAND) cnt = MAXCAND;

    // 3) exact fp32 dot per candidate; block-wide over DM (256 x 4 = 1024)
    const float* x = X + (size_t)row * DM;
    float4 xv = *reinterpret_cast<const float4*>(x + tid * 4);
    float bv = -INFINITY; int bi = 0x7fffffff;
    for (int j = 0; j < cnt; j++) {
        const int ci = scand[j];
        float4 dv = *reinterpret_cast<const float4*>(
            Dict + (size_t)ci * DM + tid * 4);
        sred[tid] = xv.x * dv.x + xv.y * dv.y + xv.z * dv.z + xv.w * dv.w;
        __syncthreads();
        for (int off = 128; off > 0; off >>= 1) {
            if (tid < off) sred[tid] += sred[tid + off];
            __syncthreads();
        }
        const float sc = sred[0];
        if (BETTER(sc, ci, bv, bi)) { bv = sc; bi = ci; }
        __syncthreads();
    }
    if (tid == 0) {
        argmax_out[row] = (float)bi;
        invp[row] = 1.0f / rsum[row];
    }
}

// ---------------------------------------------------------------------------
// Launch
// ---------------------------------------------------------------------------
extern "C" void kernel_launch(void* const* d_in, const int* in_sizes, int n_in,
                              void* d_out, int out_size)
{
    const float* X    = (const float*)d_in[0];
    const float* Dict = (const float*)d_in[1];
    const int*   mask = (const int*)d_in[2];
    float* out = (float*)d_out;

    __half *Xf, *Df, *DTf, *Wf;
    cudaGetSymbolAddress((void**)&Xf, g_Xf);
    cudaGetSymbolAddress((void**)&Df, g_Df);
    cudaGetSymbolAddress((void**)&DTf, g_DTf);
    cudaGetSymbolAddress((void**)&Wf, g_Wf);
    float* rsum; cudaGetSymbolAddress((void**)&rsum, g_sum);
    unsigned* tmax; cudaGetSymbolAddress((void**)&tmax, g_tmax);
    float* invp; cudaGetSymbolAddress((void**)&invp, g_inv);

    float* recon_out  = out;
    float* argmax_out = out + (size_t)M_ROWS * DM;

    static bool attr_set = false;
    if (!attr_set) {
        cudaFuncSetAttribute(gemm_f16<true>,
                             cudaFuncAttributeMaxDynamicSharedMemorySize, SMEMG);
        cudaFuncSetAttribute(gemm_f16<false>,
                             cudaFuncAttributeMaxDynamicSharedMemorySize, SMEMG);
        attr_set = true;
    }

    // 0) zero per-row sums and tile maxima
    init_kernel<<<1024, 256>>>(rsum, tmax);

    // 1) fp16 conversions: X*log2e, dict (K-major + transposed, single read)
    {
        int n4x = (M_ROWS * DM) / 4;
        to_f16_scaled_kernel<<<(n4x + 255) / 256, 256>>>(X, Xf, LOG2E, n4x);
        dim3 grid(DM / 32, N_ATOMS / 32), blk(32, 8);
        convert_dict_kernel<<<grid, blk>>>(Dict, Df, DTf);
    }

    // 2) fused scores+exp GEMM: Wf = 2^(Xf · Df^T), masked -> 0,
    //    with per-row sum and per-tile max atomics
    {
        dim3 grid(N_ATOMS / 128, M_ROWS / 128);
        gemm_f16<true><<<grid, 128, SMEMG>>>(
            Xf, Df, DM, mask, nullptr, rsum, tmax, Wf, N_ATOMS);
    }

    // 3) exact argmax via tile maxima (tiny traffic) + invp
    argmax_rescue_kernel<<<M_ROWS, 256>>>(
        Wf, X, Dict, rsum, tmax, invp, argmax_out);

    // 4) reconstruction = (Wf · DTf) * inv[row]  (deterministic, no split-K)
    {
        dim3 grid(DM / 128, M_ROWS / 128);
        gemm_f16<false><<<grid, 128, SMEMG>>>(
            Wf, DTf, N_ATOMS, nullptr, invp, nullptr, nullptr, recon_out, DM);
    }
}

// round 16
// speedup vs baseline: 1.0309x; 1.0309x over previous
#include <cuda_runtime.h>
#include <cuda_fp16.h>
#include <math.h>
#include <stdint.h>

// ---------------------------------------------------------------------------
// Problem dims
// ---------------------------------------------------------------------------
#define M_ROWS  8192      // 4 * 2048
#define N_ATOMS 16384
#define DM      1024
#define LOG2E   1.4426950408889634f
#define CANDF   0.99448f  // 2^-0.008 — candidate threshold factor on w
#define MAXCAND 16
#define NTILES  (N_ATOMS / 128)   // 128 n-tiles per row
#define KSPLIT  4

// ---------------------------------------------------------------------------
// Scratch (__device__ globals; allocation APIs are forbidden)
// ---------------------------------------------------------------------------
__device__ __half   g_Xf[(size_t)M_ROWS * DM];             // x * log2e, fp16
__device__ __half   g_Df[(size_t)N_ATOMS * DM];            // dict fp16 K-major
__device__ __half   g_DTf[(size_t)DM * N_ATOMS];           // dict^T fp16
__device__ __half   g_Wf[(size_t)M_ROWS * N_ATOMS];        // 256 MB fp16 weights
__device__ float    g_part[(size_t)KSPLIT * M_ROWS * DM];  // 128 MB partials
__device__ float    g_sum[M_ROWS];
__device__ unsigned g_tmax[(size_t)M_ROWS * NTILES];       // per-tile max bits
__device__ float    g_inv[M_ROWS];

// ---------------------------------------------------------------------------
// Low-level helpers (sm_80+ baseline PTX only — NO tcgen05 on plain sm_103)
// ---------------------------------------------------------------------------
__device__ __forceinline__ uint32_t smem_to_u32(const void* p) {
    uint32_t a;
    asm("{ .reg .u64 t; cvta.to.shared.u64 t, %1; cvt.u32.u64 %0, t; }"
        : "=r"(a) : "l"(p));
    return a;
}

#define CP16(dst, src) \
    asm volatile("cp.async.cg.shared.global [%0], [%1], 16;" \
                 :: "r"(dst), "l"(src) : "memory")
#define CP_COMMIT() asm volatile("cp.async.commit_group;" ::: "memory")
#define CP_WAIT2()  asm volatile("cp.async.wait_group 2;"  ::: "memory")

#define LDSM4(r0, r1, r2, r3, addr) \
    asm volatile("ldmatrix.sync.aligned.m8n8.x4.shared.b16 {%0,%1,%2,%3}, [%4];" \
        : "=r"(r0), "=r"(r1), "=r"(r2), "=r"(r3) : "r"(addr))

__device__ __forceinline__ void mma16816_f16(float* c, const uint32_t* a,
                                             const uint32_t* b) {
    asm volatile(
        "mma.sync.aligned.m16n8k16.row.col.f32.f16.f16.f32 "
        "{%0,%1,%2,%3}, {%4,%5,%6,%7}, {%8,%9}, {%0,%1,%2,%3};"
        : "+f"(c[0]), "+f"(c[1]), "+f"(c[2]), "+f"(c[3])
        : "r"(a[0]), "r"(a[1]), "r"(a[2]), "r"(a[3]), "r"(b[0]), "r"(b[1]));
}

__device__ __forceinline__ float ex2f(float x) {
    float y;
    asm("ex2.approx.ftz.f32 %0, %1;" : "=f"(y) : "f"(x));
    return y;
}

// ---------------------------------------------------------------------------
// Init: zero per-row sums and per-tile maxima
// ---------------------------------------------------------------------------
__global__ __launch_bounds__(256) void init_kernel(
    float* __restrict__ sum, unsigned* __restrict__ tmax)
{
    int i = blockIdx.x * blockDim.x + threadIdx.x;
    if (i < M_ROWS) sum[i] = 0.0f;
    int total_tm = M_ROWS * NTILES;
    for (int j = i; j < total_tm; j += gridDim.x * blockDim.x)
        tmax[j] = 0u;
}

// ---------------------------------------------------------------------------
// Conversion kernels
// ---------------------------------------------------------------------------
__global__ __launch_bounds__(256) void to_f16_scaled_kernel(
    const float* __restrict__ src, __half* __restrict__ dst, float scale, int n4)
{
    int i = blockIdx.x * blockDim.x + threadIdx.x;
    if (i >= n4) return;
    float4 v = reinterpret_cast<const float4*>(src)[i];
    ushort4 hv;
    hv.x = __half_as_ushort(__float2half_rn(v.x * scale));
    hv.y = __half_as_ushort(__float2half_rn(v.y * scale));
    hv.z = __half_as_ushort(__float2half_rn(v.z * scale));
    hv.w = __half_as_ushort(__float2half_rn(v.w * scale));
    reinterpret_cast<ushort4*>(dst)[i] = hv;
}

// dict [N_ATOMS][DM] fp32 -> Df fp16 (same layout) + DTf fp16 (transposed).
__global__ __launch_bounds__(256) void convert_dict_kernel(
    const float* __restrict__ dict, __half* __restrict__ Df,
    __half* __restrict__ DTf)
{
    __shared__ float t[32][33];
    const int bx = blockIdx.x;   // DM tile
    const int by = blockIdx.y;   // atom tile
    const int tx = threadIdx.x;
    const int ty = threadIdx.y;
    #pragma unroll
    for (int k = 0; k < 32; k += 8) {
        float v = dict[(size_t)(by * 32 + ty + k) * DM + bx * 32 + tx];
        t[ty + k][tx] = v;
        Df[(size_t)(by * 32 + ty + k) * DM + bx * 32 + tx] = __float2half_rn(v);
    }
    __syncthreads();
    #pragma unroll
    for (int k = 0; k < 32; k += 8) {
        size_t o = (size_t)(bx * 32 + ty + k) * N_ATOMS + by * 32 + tx;
        DTf[o] = __float2half_rn(t[tx][ty + k]);
    }
}

// ---------------------------------------------------------------------------
// Unified 1-term fp16 GEMM via ldmatrix + mma.sync, BK=32, 4-stage cp.async.
// out tile 128x128 = A[M,K] · B[N,K]^T
// MODE 0: out is __half WEIGHT w = 2^s (A pre-scaled by log2e), masked->0;
//         epilogue accumulates per-row sum (atomicAdd) and PER-TILE max.
// MODE 1: split-K partial (gridDim.z = KSPLIT): plain fp32 stores into the
//         z-th private partial buffer; no inv, no atomics. Deterministic.
// 128 threads = 4 warps (2x2) of 64x64, software-pipelined inner loop.
// smem rows: 64B data + 16B pad (80B) — conflict-free LDSM phases.
// ---------------------------------------------------------------------------
#define ROWB     80
#define TILE_B   (128 * ROWB)          // 10240
#define STAGE    (2 * TILE_B)          // 20480
#define NSTAGES  4
#define SMEMG    (NSTAGES * STAGE)     // 81920

template <int MODE>
__global__ __launch_bounds__(128, 2) void gemm_f16(
    const __half* __restrict__ A, const __half* __restrict__ B, int Kdim,
    const int* __restrict__ mask,
    float* __restrict__ rsum, unsigned* __restrict__ tmax,
    void* __restrict__ outp, int out_ld)
{
    extern __shared__ char smem[];
    const uint32_t sbase = smem_to_u32(smem);
    const int tid  = threadIdx.x;
    const int warp = tid >> 5;
    const int lane = tid & 31;
    const int bm = blockIdx.y * 128;
    const int bn = blockIdx.x * 128;
    const int wm = (warp & 1) * 64;
    const int wn = (warp >> 1) * 64;

    // split-K range (MODE 1); full K otherwise
    const int ksz   = (MODE == 1) ? (Kdim / KSPLIT) : Kdim;
    const int cbase = (MODE == 1) ? ((blockIdx.z * ksz) >> 5) : 0;
    const int ncs   = ksz >> 5;

    // ldmatrix per-thread address components
    const int a_row = wm + (lane & 15);
    const int a_kh  = (lane >> 4) * 16;
    const int b_row = wn + ((lane >> 4) << 3) + (lane & 7);
    const int b_kh  = ((lane >> 3) & 1) * 16;

    float acc[4][8][4];
    #pragma unroll
    for (int mt = 0; mt < 4; mt++)
        #pragma unroll
        for (int nt = 0; nt < 8; nt++)
            #pragma unroll
            for (int r = 0; r < 4; r++) acc[mt][nt][r] = 0.0f;

    #define ISSUEG(cc, buf) do { \
        const int k0_ = (cc) << 5; \
        _Pragma("unroll") \
        for (int p = 0; p < 4; p++) { \
            const int v_   = tid + p * 128; \
            const int row_ = v_ >> 2; \
            const int c16_ = v_ & 3; \
            const uint32_t dst_ = sbase + (buf) * STAGE \
                                + row_ * ROWB + c16_ * 16; \
            const size_t ga_ = (size_t)(bm + row_) * Kdim + k0_ + c16_ * 8; \
            const size_t gb_ = (size_t)(bn + row_) * Kdim + k0_ + c16_ * 8; \
            CP16(dst_ + 0 * TILE_B, A + ga_); \
            CP16(dst_ + 1 * TILE_B, B + gb_); \
        } \
        CP_COMMIT(); \
    } while (0)

    ISSUEG(cbase + 0, 0);
    ISSUEG(cbase + 1, 1);
    ISSUEG(cbase + 2, 2);

    for (int c = 0; c < ncs; c++) {
        CP_WAIT2();          // chunk c resident (<=2 younger groups pending)
        __syncthreads();     // all warps past compute of chunk c-1
        if (c + 3 < ncs) ISSUEG(cbase + c + 3, (c + 3) & 3);

        const uint32_t sA = sbase + (c & 3) * STAGE;
        const uint32_t sB = sA + TILE_B;

        #pragma unroll
        for (int ks = 0; ks < 2; ks++) {
            const uint32_t kb0 = ks * 32;

            uint32_t a[4][4], b[8][2];
            // B fragments first (4 LDSM covering nt 0..7)
            #pragma unroll
            for (int p = 0; p < 4; p++) {
                const uint32_t bd = sB + (b_row + p * 16) * ROWB + b_kh + kb0;
                LDSM4(b[2 * p][0], b[2 * p][1], b[2 * p + 1][0], b[2 * p + 1][1], bd);
            }
            // A[0], then interleave A[mt+1] load with A[mt]'s MMAs
            {
                const uint32_t ad = sA + (a_row + 0) * ROWB + a_kh + kb0;
                LDSM4(a[0][0], a[0][1], a[0][2], a[0][3], ad);
            }
            #pragma unroll
            for (int mt = 0; mt < 4; mt++) {
                if (mt < 3) {
                    const uint32_t ad = sA + (a_row + (mt + 1) * 16) * ROWB
                                      + a_kh + kb0;
                    LDSM4(a[mt + 1][0], a[mt + 1][1], a[mt + 1][2], a[mt + 1][3], ad);
                }
                #pragma unroll
                for (int nt = 0; nt < 8; nt++)
                    mma16816_f16(acc[mt][nt], a[mt], b[nt]);
            }
        }
    }
    #undef ISSUEG

    // Epilogue
    const int lr = lane >> 2;
    float* opart = (MODE == 1)
        ? (float*)outp + (size_t)blockIdx.z * M_ROWS * DM : (float*)outp;
    #pragma unroll
    for (int mt = 0; mt < 4; mt++) {
        #pragma unroll
        for (int half = 0; half < 2; half++) {
            const int rloc = bm + wm + mt * 16 + lr + half * 8;
            const size_t rg = (size_t)rloc;
            float rsum_l = 0.0f, rmax_l = 0.0f;
            #pragma unroll
            for (int nt = 0; nt < 8; nt++) {
                const size_t o = rg * (size_t)out_ld
                               + (bn + wn + nt * 8 + (lane & 3) * 2);
                if (MODE == 0) {
                    // fused softmax numerator: w = 2^s (A pre-scaled), mask->0
                    int2 mv = *reinterpret_cast<const int2*>(mask + o);
                    float2 v;
                    v.x = mv.x ? ex2f(acc[mt][nt][half * 2 + 0]) : 0.0f;
                    v.y = mv.y ? ex2f(acc[mt][nt][half * 2 + 1]) : 0.0f;
                    __half2 h2 = __float22half2_rn(v);
                    *reinterpret_cast<__half2*>((__half*)outp + o) = h2;
                    // accumulate from the ROUNDED values (consistency)
                    float2 vr = __half22float2(h2);
                    rsum_l += vr.x + vr.y;
                    rmax_l = fmaxf(rmax_l, fmaxf(vr.x, vr.y));
                } else {
                    float2 v;
                    v.x = acc[mt][nt][half * 2 + 0];
                    v.y = acc[mt][nt][half * 2 + 1];
                    *reinterpret_cast<float2*>(opart + o) = v;
                }
            }
            if (MODE == 0) {
                // quad reduce (lanes with same lr hold same row)
                rsum_l += __shfl_xor_sync(0xffffffffu, rsum_l, 1);
                rsum_l += __shfl_xor_sync(0xffffffffu, rsum_l, 2);
                rmax_l = fmaxf(rmax_l, __shfl_xor_sync(0xffffffffu, rmax_l, 1));
                rmax_l = fmaxf(rmax_l, __shfl_xor_sync(0xffffffffu, rmax_l, 2));
                if ((lane & 3) == 0) {
                    atomicAdd(rsum + rloc, rsum_l);
                    atomicMax(tmax + (size_t)rloc * NTILES + blockIdx.x,
                              __float_as_uint(rmax_l));
                }
            }
        }
    }
}

// ---------------------------------------------------------------------------
// Deterministic split-K reduction: out = ((p0+p1)+(p2+p3)) * inv[row]
// ---------------------------------------------------------------------------
__global__ __launch_bounds__(256) void reduce_kernel(
    const float* __restrict__ P, const float* __restrict__ invp,
    float* __restrict__ out)
{
    const int i = blockIdx.x * blockDim.x + threadIdx.x;  // float4 index
    const int row = i >> 8;                               // 256 float4 per row
    const float inv = invp[row];
    const size_t stride = (size_t)M_ROWS * DM / 4;
    float4 a = reinterpret_cast<const float4*>(P)[i];
    float4 b = reinterpret_cast<const float4*>(P)[i + stride];
    float4 c = reinterpret_cast<const float4*>(P)[i + 2 * stride];
    float4 d = reinterpret_cast<const float4*>(P)[i + 3 * stride];
    float4 o;
    o.x = ((a.x + b.x) + (c.x + d.x)) * inv;
    o.y = ((a.y + b.y) + (c.y + d.y)) * inv;
    o.z = ((a.z + b.z) + (c.z + d.z)) * inv;
    o.w = ((a.w + b.w) + (c.w + d.w)) * inv;
    reinterpret_cast<float4*>(out)[i] = o;
}

// ---------------------------------------------------------------------------
// Exact argmax, one block (256 thr) per row, using per-tile maxima:
// 1) reduce 128 tile maxima -> global max, thresh = max*CANDF
// 2) scan ONLY tiles whose max >= thresh (usually 1-2) for candidates
// 3) exact fp32 dot per candidate (block-wide over DM), winner by
//    (value, then smaller index). Also publishes invp = 1/sum.
// ---------------------------------------------------------------------------
#define BETTER(v, i, V, I) ((v) > (V) || ((v) == (V) && (i) < (I)))

__global__ __launch_bounds__(256) void argmax_rescue_kernel(
    const __half* __restrict__ Wf, const float* __restrict__ X,
    const float* __restrict__ Dict, const float* __restrict__ rsum,
    const unsigned* __restrict__ tmax, float* __restrict__ invp,
    float* __restrict__ argmax_out)
{
    const int row = blockIdx.x;
    const __half* wf = Wf + (size_t)row * N_ATOMS;
    const int tid = threadIdx.x;

    __shared__ float sred[256];
    __shared__ int   stile[MAXCAND];
    __shared__ int   stcount;
    __shared__ int   scand[MAXCAND];
    __shared__ int   scount;
    __shared__ float sthresh;

    if (tid == 0) { stcount = 0; scount = 0; }

    // 1) global max over tile maxima
    float tm = (tid < NTILES)
        ? __uint_as_float(tmax[(size_t)row * NTILES + tid]) : 0.0f;
    sred[tid] = tm;
    __syncthreads();
    for (int off = 128; off > 0; off >>= 1) {
        if (tid < off) sred[tid] = fmaxf(sred[tid], sred[tid + off]);
        __syncthreads();
    }
    if (tid == 0) sthresh = sred[0] * CANDF;
    __syncthreads();
    const float thresh = sthresh;

    // 2) qualifying tiles
    if (tid < NTILES && tm >= thresh) {
        int slot = atomicAdd(&stcount, 1);
        if (slot < MAXCAND) stile[slot] = tid;
    }
    __syncthreads();
    int tcnt = stcount; if (tcnt > MAXCAND) tcnt = MAXCAND;

    // scan qualifying tiles for candidates (128 weights per tile)
    for (int j = 0; j < tcnt; j++) {
        const int base = stile[j] * 128;
        if (tid < 128) {
            float w = __half2float(wf[base + tid]);
            if (w >= thresh) {
                int slot = atomicAdd(&scount, 1);
                if (slot < MAXCAND) scand[slot] = base + tid;
            }
        }
    }
    __syncthreads();
    int cnt = scount; if (cnt > MAXCAND) cnt = MAXCAND;

    // 3) exact fp32 dot per candidate; block-wide over DM (256 x 4 = 1024)
    const float* x = X + (size_t)row * DM;
    float4 xv = *reinterpret_cast<const float4*>(x + tid * 4);
    float bv = -INFINITY; int bi = 0x7fffffff;
    for (int j = 0; j < cnt; j++) {
        const int ci = scand[j];
        float4 dv = *reinterpret_cast<const float4*>(
            Dict + (size_t)ci * DM + tid * 4);
        sred[tid] = xv.x * dv.x + xv.y * dv.y + xv.z * dv.z + xv.w * dv.w;
        __syncthreads();
        for (int off = 128; off > 0; off >>= 1) {
            if (tid < off) sred[tid] += sred[tid + off];
            __syncthreads();
        }
        const float sc = sred[0];
        if (BETTER(sc, ci, bv, bi)) { bv = sc; bi = ci; }
        __syncthreads();
    }
    if (tid == 0) {
        argmax_out[row] = (float)bi;
        invp[row] = 1.0f / rsum[row];
    }
}

// ---------------------------------------------------------------------------
// Launch
// ---------------------------------------------------------------------------
extern "C" void kernel_launch(void* const* d_in, const int* in_sizes, int n_in,
                              void* d_out, int out_size)
{
    const float* X    = (const float*)d_in[0];
    const float* Dict = (const float*)d_in[1];
    const int*   mask = (const int*)d_in[2];
    float* out = (float*)d_out;

    __half *Xf, *Df, *DTf, *Wf;
    cudaGetSymbolAddress((void**)&Xf, g_Xf);
    cudaGetSymbolAddress((void**)&Df, g_Df);
    cudaGetSymbolAddress((void**)&DTf, g_DTf);
    cudaGetSymbolAddress((void**)&Wf, g_Wf);
    float* part; cudaGetSymbolAddress((void**)&part, g_part);
    float* rsum; cudaGetSymbolAddress((void**)&rsum, g_sum);
    unsigned* tmax; cudaGetSymbolAddress((void**)&tmax, g_tmax);
    float* invp; cudaGetSymbolAddress((void**)&invp, g_inv);

    float* recon_out  = out;
    float* argmax_out = out + (size_t)M_ROWS * DM;

    static bool attr_set = false;
    if (!attr_set) {
        cudaFuncSetAttribute(gemm_f16<0>,
                             cudaFuncAttributeMaxDynamicSharedMemorySize, SMEMG);
        cudaFuncSetAttribute(gemm_f16<1>,
                             cudaFuncAttributeMaxDynamicSharedMemorySize, SMEMG);
        attr_set = true;
    }

    // 0) zero per-row sums and tile maxima
    init_kernel<<<1024, 256>>>(rsum, tmax);

    // 1) fp16 conversions: X*log2e, dict (K-major + transposed, single read)
    {
        int n4x = (M_ROWS * DM) / 4;
        to_f16_scaled_kernel<<<(n4x + 255) / 256, 256>>>(X, Xf, LOG2E, n4x);
        dim3 grid(DM / 32, N_ATOMS / 32), blk(32, 8);
        convert_dict_kernel<<<grid, blk>>>(Dict, Df, DTf);
    }

    // 2) fused scores+exp GEMM: Wf = 2^(Xf · Df^T), masked -> 0,
    //    with per-row sum and per-tile max atomics
    {
        dim3 grid(N_ATOMS / 128, M_ROWS / 128);
        gemm_f16<0><<<grid, 128, SMEMG>>>(
            Xf, Df, DM, mask, rsum, tmax, Wf, N_ATOMS);
    }

    // 3) recon partials (deterministic split-K, private buffers, no atomics)
    {
        dim3 grid(DM / 128, M_ROWS / 128, KSPLIT);
        gemm_f16<1><<<grid, 128, SMEMG>>>(
            Wf, DTf, N_ATOMS, nullptr, nullptr, nullptr, part, DM);
    }

    // 4) exact argmax via tile maxima (tiny traffic) + invp
    argmax_rescue_kernel<<<M_ROWS, 256>>>(
        Wf, X, Dict, rsum, tmax, invp, argmax_out);

    // 5) deterministic fixed-order reduction: recon = (Σ partials) * inv
    {
        int n4 = M_ROWS * DM / 4;
        reduce_kernel<<<n4 / 256, 256>>>(part, invp, recon_out);
    }
}